// round 14
// baseline (speedup 1.0000x reference)
#include <cuda_runtime.h>
#include <cuda_fp16.h>
#include <math.h>
#include <stdint.h>

#define Bc 4
#define Sq 2048
#define Dm 1024
#define Hh 16
#define HD 64
#define MT (Bc*Sq)   // 8192 rows

#define QSCALE 0.18033688011112042f   // log2(e)/8  (scores in log2 domain)

// ---------------------------------------------------------------------------
// Static device scratch (allocation-guard safe).
// ---------------------------------------------------------------------------
__device__ __half g_Xhi[MT*Dm];                         // X (fp16)
__device__ __half g_Wth[4*Dm*Dm];                       // W^T (fp16, n-major)
__device__ __half g_Qh[MT*Dm];                          // rotated+scaled Q (fp16)
__device__ __half g_Kh[MT*Dm];                          // rotated K (fp16)
__device__ __half g_Vh[MT*Dm];                          // V (fp16)
__device__ __half g_Oh[MT*Dm];                          // attention output (fp16)
__device__ float2 g_cs[32*Sq];                          // [ip][pos] cos/sin

// ---------------------------------------------------------------------------
// PTX helpers (sm_80-era: cp.async, ldmatrix, mma.sync — valid on sm_103)
// ---------------------------------------------------------------------------
__device__ __forceinline__ uint32_t smem_u32(const void* p) {
    uint32_t a;
    asm("{ .reg .u64 t; cvta.to.shared.u64 t, %1; cvt.u32.u64 %0, t; }"
        : "=r"(a) : "l"(p));
    return a;
}
__device__ __forceinline__ void cp16(uint32_t dst, const void* src) {
    asm volatile("cp.async.cg.shared.global [%0], [%1], 16;" :: "r"(dst), "l"(src));
}
__device__ __forceinline__ void ldmx4(uint32_t* r, uint32_t addr) {
    asm volatile("ldmatrix.sync.aligned.m8n8.x4.shared.b16 {%0,%1,%2,%3}, [%4];"
                 : "=r"(r[0]), "=r"(r[1]), "=r"(r[2]), "=r"(r[3]) : "r"(addr));
}
__device__ __forceinline__ void ldmx4t(uint32_t* r, uint32_t addr) {
    asm volatile("ldmatrix.sync.aligned.m8n8.x4.trans.shared.b16 {%0,%1,%2,%3}, [%4];"
                 : "=r"(r[0]), "=r"(r[1]), "=r"(r[2]), "=r"(r[3]) : "r"(addr));
}
__device__ __forceinline__ void mma16816(float* c, const uint32_t* a, const uint32_t* b) {
    asm volatile("mma.sync.aligned.m16n8k16.row.col.f32.f16.f16.f32 "
                 "{%0,%1,%2,%3}, {%4,%5,%6,%7}, {%8,%9}, {%0,%1,%2,%3};"
                 : "+f"(c[0]), "+f"(c[1]), "+f"(c[2]), "+f"(c[3])
                 : "r"(a[0]), "r"(a[1]), "r"(a[2]), "r"(a[3]), "r"(b[0]), "r"(b[1]));
}
__device__ __forceinline__ uint32_t packh2(float a, float b) {
    __half2 h = __floats2half2_rn(a, b);
    return *(uint32_t*)&h;
}
// Fast 2^x on the FMA pipe (no MUFU). |err| ~2e-6 on the used range, x<=0.
__device__ __forceinline__ float exp2f_fast(float x) {
    x = fmaxf(x, -126.0f);
    float t  = x + 12582912.0f;              // round-to-nearest-int magic
    int   ei = __float_as_int(t) - 0x4B400000;
    float f  = x - (t - 12582912.0f);        // [-0.5, 0.5]
    float p  = 1.3333558146e-3f;
    p = fmaf(p, f, 9.6181291076e-3f);
    p = fmaf(p, f, 5.5504108665e-2f);
    p = fmaf(p, f, 2.4022650696e-1f);
    p = fmaf(p, f, 6.9314718056e-1f);
    p = fmaf(p, f, 1.0f);
    return __int_as_float(__float_as_int(p) + (ei << 23));
}

// ---------------------------------------------------------------------------
// Prep kernels
// ---------------------------------------------------------------------------
__global__ void init_cs_kernel() {
    int i = blockIdx.x * blockDim.x + threadIdx.x;  // 0..65535
    int ip = i >> 11, pos = i & (Sq - 1);
    float invf = (float)exp(-(double)(2 * ip) * (log(10000.0) / 64.0));
    float sn, cn;
    sincosf((float)pos * invf, &sn, &cn);
    g_cs[i] = make_float2(cn, sn);
}

// fp32 -> fp16 convert
__global__ void conv_x_kernel(const float* __restrict__ src, int n4) {
    int i = blockIdx.x * blockDim.x + threadIdx.x;
    if (i >= n4) return;
    float4 v = ((const float4*)src)[i];
    __half2* h2 = (__half2*)g_Xhi;
    h2[2 * i]     = __floats2half2_rn(v.x, v.y);
    h2[2 * i + 1] = __floats2half2_rn(v.z, v.w);
}

// Transpose the 4 weight matrices to fp16: Wt[n][k] = W[k][n]
__global__ void conv_wt_kernel(const float* __restrict__ Wq, const float* __restrict__ Wk,
                               const float* __restrict__ Wv, const float* __restrict__ Wo) {
    __shared__ float ts[32][33];
    int z = blockIdx.z;
    const float* W = (z == 0) ? Wq : (z == 1) ? Wk : (z == 2) ? Wv : Wo;
    int k0 = blockIdx.y * 32, n0 = blockIdx.x * 32;
    int tx = threadIdx.x, ty = threadIdx.y;
#pragma unroll
    for (int r = 0; r < 32; r += 8)
        ts[ty + r][tx] = W[(size_t)(k0 + ty + r) * Dm + n0 + tx];
    __syncthreads();
#pragma unroll
    for (int r = 0; r < 32; r += 8) {
        float v = ts[tx][ty + r];
        size_t o = (size_t)z * Dm * Dm + (size_t)(n0 + ty + r) * Dm + k0 + tx;
        g_Wth[o] = __float2half_rn(v);
    }
}

// ---------------------------------------------------------------------------
// mma.sync fp16 GEMM: C = A * B^T. KC=32, ROWB=80 (R11-proven), but a
// 3-STAGE cp.async ring: refill targets a FREE buffer right after wait_group,
// so there is ONE barrier per chunk and the 32-MMA chunk issues uninterrupted.
// CTA 128x128, 8 warps 64x32. Stage 20KB x3 = 60KB -> 2 CTAs/SM.
// MODE: 0 = f32 out (oproj); 1 = RoPE+scale fp16 out (Q);
//       2 = RoPE fp16 out (K); 3 = fp16 out (V)
// ---------------------------------------------------------------------------
#define KC 32
#define NCHUNK (Dm / KC)        // 32
#define ROWB 80
#define STG_MAT (128 * ROWB)    // 10240
#define STG_SIZE (2 * STG_MAT)  // 20480 : A, B
#define GEMM_SMEM (3 * STG_SIZE)  // 61440

__device__ __forceinline__ void load_chunk(uint32_t sb,
    const __half* __restrict__ A, const __half* __restrict__ B,
    int m0, int n0, int kc, int tid)
{
    const __half* srcs[2] = { A + (size_t)m0 * Dm + kc, B + (size_t)n0 * Dm + kc };
    const int row = (tid >> 2);
    const int s   = tid & 3;
#pragma unroll
    for (int j = 0; j < 4; ++j) {
        const int mat = j >> 1;
        const int r   = (j & 1) * 64 + row;
        cp16(sb + mat * STG_MAT + r * ROWB + s * 16,
             (const char*)(srcs[mat] + (size_t)r * Dm) + s * 16);
    }
}

__device__ __forceinline__ void gemm_frags(uint32_t aBase, uint32_t bBase, int s,
                                           uint32_t (*ah)[4], uint32_t (*bh)[2])
{
#pragma unroll
    for (int mt = 0; mt < 4; ++mt)
        ldmx4(ah[mt], aBase + mt * (16 * ROWB) + s * 32);
#pragma unroll
    for (int p = 0; p < 2; ++p) {
        uint32_t t[4];
        ldmx4(t, bBase + p * (16 * ROWB) + s * 32);
        bh[2 * p][0] = t[0]; bh[2 * p][1] = t[1];
        bh[2 * p + 1][0] = t[2]; bh[2 * p + 1][1] = t[3];
    }
}

__device__ __forceinline__ void gemm_mmas(float (*acc)[4][4],
                                          uint32_t (*ah)[4], uint32_t (*bh)[2])
{
#pragma unroll
    for (int mt = 0; mt < 4; ++mt)
#pragma unroll
        for (int nt = 0; nt < 4; ++nt)
            mma16816(acc[mt][nt], ah[mt], bh[nt]);
}

template <int MODE>
__device__ __forceinline__ void gemm_mma(const __half* __restrict__ A,
                                         const __half* __restrict__ B,
                                         float* __restrict__ Cf,
                                         __half* __restrict__ Ch)
{
    extern __shared__ char smraw[];
    const uint32_t sbase = smem_u32(smraw);

    const int tid  = threadIdx.x;
    const int wid  = tid >> 5, lane = tid & 31;
    const int wm   = wid & 1, wn = wid >> 1;
    const int m0   = blockIdx.y * 128, n0 = blockIdx.x * 128;

    const uint32_t aLaneOff = (lane & 15) * ROWB + (lane >> 4) * 16;
    const uint32_t bLaneOff = ((lane >> 4) * 8 + (lane & 7)) * ROWB + ((lane >> 3) & 1) * 16;

    float acc[4][4][4];
#pragma unroll
    for (int mt = 0; mt < 4; ++mt)
#pragma unroll
        for (int nt = 0; nt < 4; ++nt)
#pragma unroll
            for (int q = 0; q < 4; ++q) acc[mt][nt][q] = 0.0f;

#pragma unroll
    for (int c = 0; c < 2; ++c) {
        load_chunk(sbase + c * STG_SIZE, A, B, m0, n0, c * KC, tid);
        asm volatile("cp.async.commit_group;" ::: "memory");
    }

    int buf = 0;       // buffer of chunk i; (i+2) lands in (buf+2)%3
    for (int i = 0; i < NCHUNK; ++i) {
        asm volatile("cp.async.wait_group 1;" ::: "memory");
        __syncthreads();   // chunk i ready; all warps done reading buffer (i+2)%3

        // Refill the FREE buffer immediately (overlaps the whole chunk's MMAs)
        const int nbuf = (buf + 2 >= 3) ? buf - 1 : buf + 2;
        if (i + 2 < NCHUNK)
            load_chunk(sbase + nbuf * STG_SIZE, A, B, m0, n0, (i + 2) * KC, tid);
        asm volatile("cp.async.commit_group;" ::: "memory");

        const uint32_t sb = sbase + buf * STG_SIZE;
        const uint32_t aBase = sb + (wm * 64) * ROWB + aLaneOff;
        const uint32_t bBase = sb + STG_MAT + (wn * 32) * ROWB + bLaneOff;

#pragma unroll
        for (int s = 0; s < 2; ++s) {
            uint32_t ah[4][4], bh[4][2];
            gemm_frags(aBase, bBase, s, ah, bh);
            gemm_mmas(acc, ah, bh);
        }
        buf = (buf + 1 >= 3) ? 0 : buf + 1;
    }

#pragma unroll
    for (int mt = 0; mt < 4; ++mt) {
        const int r = m0 + wm * 64 + mt * 16 + (lane >> 2);
#pragma unroll
        for (int nt = 0; nt < 4; ++nt) {
            const int c = n0 + wn * 32 + nt * 8 + (lane & 3) * 2;
            float v0 = acc[mt][nt][0], v1 = acc[mt][nt][1];
            float v2 = acc[mt][nt][2], v3 = acc[mt][nt][3];
            if (MODE == 1 || MODE == 2) {
                const int ip = (c & (HD - 1)) >> 1;
                float2 cs0 = g_cs[ip * Sq + (r & (Sq - 1))];
                float2 cs8 = g_cs[ip * Sq + ((r + 8) & (Sq - 1))];
                float t0 = v0 * cs0.x - v1 * cs0.y;
                float t1 = v0 * cs0.y + v1 * cs0.x;
                float t2 = v2 * cs8.x - v3 * cs8.y;
                float t3 = v2 * cs8.y + v3 * cs8.x;
                v0 = t0; v1 = t1; v2 = t2; v3 = t3;
            }
            if (MODE == 1) { v0 *= QSCALE; v1 *= QSCALE; v2 *= QSCALE; v3 *= QSCALE; }
            if (MODE == 0) {
                *(float2*)(Cf + (size_t)r * Dm + c)       = make_float2(v0, v1);
                *(float2*)(Cf + (size_t)(r + 8) * Dm + c) = make_float2(v2, v3);
            } else {
                *(__half2*)(Ch + (size_t)r * Dm + c)       = __floats2half2_rn(v0, v1);
                *(__half2*)(Ch + (size_t)(r + 8) * Dm + c) = __floats2half2_rn(v2, v3);
            }
        }
    }
}

__global__ __launch_bounds__(256, 2)
void qkv_mma_kernel() {
    const int z = blockIdx.z;
    const __half* Bh = g_Wth + (size_t)z * Dm * Dm;
    if (z == 0)      gemm_mma<1>(g_Xhi, Bh, nullptr, g_Qh);
    else if (z == 1) gemm_mma<2>(g_Xhi, Bh, nullptr, g_Kh);
    else             gemm_mma<3>(g_Xhi, Bh, nullptr, g_Vh);
}

__global__ __launch_bounds__(256, 2)
void oproj_mma_kernel(float* __restrict__ out) {
    gemm_mma<0>(g_Oh, g_Wth + (size_t)3 * Dm * Dm, out, nullptr);
}

// ---------------------------------------------------------------------------
// mma.sync flash attention. Br=128, Bk=64, hd=64. Single-pass QK and PV,
// log2-domain softmax, fp16 O. 3-STAGE KV ring: the trailing per-tile barrier
// is gone — buffer (kt+2)%3 was last read at kt-1 and the top-of-loop barrier
// at kt proves all warps passed it. One barrier per KV tile.
// ---------------------------------------------------------------------------
#define FROWB 144                       // 64 halfs = 128B data + 16B pad
#define FQH_OFF 0
#define FST_OFF (128 * FROWB)           // 18432
#define FMAT (64 * FROWB)               // 9216
#define FST_SIZE (2 * FMAT)             // 18432 : Kh, Vh
#define FLASH_SMEM (FST_OFF + 3 * FST_SIZE)   // 73728

__device__ __forceinline__ void flash_load_kv(uint32_t sb, int kRow0, int h, int tid) {
    const __half* srcs[2] = { g_Kh, g_Vh };
#pragma unroll
    for (int j = 0; j < 4; ++j) {
        int it  = j * 256 + tid;          // 0..1023
        int mat = it >> 9;
        int row = (it >> 3) & 63;
        int seg = it & 7;
        cp16(sb + mat * FMAT + row * FROWB + seg * 16,
             srcs[mat] + (size_t)(kRow0 + row) * Dm + h * HD + seg * 8);
    }
}

__global__ __launch_bounds__(256, 2)
void flash_mma_kernel()
{
    extern __shared__ char smraw[];
    const uint32_t sbase = smem_u32(smraw);

    const int tid  = threadIdx.x;
    const int w    = tid >> 5, lane = tid & 31;
    const int bh   = blockIdx.y;
    const int b    = bh >> 4, h = bh & 15;
    const int qb   = gridDim.x - 1 - blockIdx.x;    // heavy blocks first
    const int q0   = qb * 128;
    const int qRow0 = b * Sq + q0;
    const int nkt  = 2 * qb + 2;

    const uint32_t aLaneOff = (lane & 15) * FROWB + (lane >> 4) * 16;
    const uint32_t bLaneOff = ((lane >> 4) * 8 + (lane & 7)) * FROWB + ((lane >> 3) & 1) * 16;

    // Group 0: Q + KV tile 0. Group 1: KV tile 1 (always exists; nkt >= 2).
#pragma unroll
    for (int j = 0; j < 4; ++j) {
        int it = j * 256 + tid;            // 0..1023
        int row = it >> 3, seg = it & 7;
        cp16(sbase + FQH_OFF + row * FROWB + seg * 16,
             g_Qh + (size_t)(qRow0 + row) * Dm + h * HD + seg * 8);
    }
    flash_load_kv(sbase + FST_OFF, b * Sq, h, tid);
    asm volatile("cp.async.commit_group;" ::: "memory");
    flash_load_kv(sbase + FST_OFF + FST_SIZE, b * Sq + 64, h, tid);
    asm volatile("cp.async.commit_group;" ::: "memory");

    uint32_t qh[4][4];
    float oacc[8][4];
#pragma unroll
    for (int nt = 0; nt < 8; ++nt)
#pragma unroll
        for (int q = 0; q < 4; ++q) oacc[nt][q] = 0.0f;
    float m0 = -1e30f, m1 = -1e30f, l0 = 0.0f, l1 = 0.0f;
    const int qrow = q0 + w * 16 + (lane >> 2);   // seq pos of row r (r+8 = +8)

    int buf = 0;
    for (int kt = 0; kt < nkt; ++kt) {
        asm volatile("cp.async.wait_group 1;" ::: "memory");
        __syncthreads();   // tile kt ready; buffer (kt+2)%3 fully consumed

        if (kt == 0) {   // Q fragments (arrived with group 0)
            const uint32_t qBaseH = sbase + FQH_OFF + (w * 16) * FROWB + aLaneOff;
#pragma unroll
            for (int j = 0; j < 4; ++j)
                ldmx4(qh[j], qBaseH + j * 32);
        }

        const int nbuf = (buf + 2 >= 3) ? buf - 1 : buf + 2;
        if (kt + 2 < nkt)
            flash_load_kv(sbase + FST_OFF + nbuf * FST_SIZE,
                          b * Sq + (kt + 2) * 64, h, tid);
        asm volatile("cp.async.commit_group;" ::: "memory");

        const uint32_t sb = sbase + FST_OFF + buf * FST_SIZE;

        // ---- S = Q K^T (log2 units) ----
        float sacc[8][4];
#pragma unroll
        for (int nt = 0; nt < 8; ++nt)
#pragma unroll
            for (int q = 0; q < 4; ++q) sacc[nt][q] = 0.0f;

#pragma unroll
        for (int p = 0; p < 4; ++p) {
            const uint32_t kBase = sb + p * (16 * FROWB) + bLaneOff;
#pragma unroll
            for (int j = 0; j < 4; ++j) {
                uint32_t kh[4];
                ldmx4(kh, kBase + j * 32);
                mma16816(sacc[2 * p],     qh[j], kh);
                mma16816(sacc[2 * p + 1], qh[j], kh + 2);
            }
        }

        // ---- causal mask (diagonal-overlap tiles only) ----
        if (kt >= 2 * qb) {
#pragma unroll
            for (int nt = 0; nt < 8; ++nt) {
                const int col = kt * 64 + nt * 8 + (lane & 3) * 2;
                if (col     > qrow)     sacc[nt][0] = -1e30f;
                if (col + 1 > qrow)     sacc[nt][1] = -1e30f;
                if (col     > qrow + 8) sacc[nt][2] = -1e30f;
                if (col + 1 > qrow + 8) sacc[nt][3] = -1e30f;
            }
        }

        // ---- online softmax (quad-local reductions) ----
        float mx0 = -1e30f, mx1 = -1e30f;
#pragma unroll
        for (int nt = 0; nt < 8; ++nt) {
            mx0 = fmaxf(mx0, fmaxf(sacc[nt][0], sacc[nt][1]));
            mx1 = fmaxf(mx1, fmaxf(sacc[nt][2], sacc[nt][3]));
        }
        mx0 = fmaxf(mx0, __shfl_xor_sync(0xffffffffu, mx0, 1, 4));
        mx0 = fmaxf(mx0, __shfl_xor_sync(0xffffffffu, mx0, 2, 4));
        mx1 = fmaxf(mx1, __shfl_xor_sync(0xffffffffu, mx1, 1, 4));
        mx1 = fmaxf(mx1, __shfl_xor_sync(0xffffffffu, mx1, 2, 4));
        const float mn0 = fmaxf(m0, mx0), mn1 = fmaxf(m1, mx1);
        const float al0 = exp2f_fast(m0 - mn0), al1 = exp2f_fast(m1 - mn1);
        float sum0 = 0.0f, sum1 = 0.0f;
#pragma unroll
        for (int nt = 0; nt < 8; ++nt) {
            sacc[nt][0] = exp2f_fast(sacc[nt][0] - mn0);
            sacc[nt][1] = exp2f_fast(sacc[nt][1] - mn0);
            sacc[nt][2] = exp2f_fast(sacc[nt][2] - mn1);
            sacc[nt][3] = exp2f_fast(sacc[nt][3] - mn1);
            sum0 += sacc[nt][0] + sacc[nt][1];
            sum1 += sacc[nt][2] + sacc[nt][3];
        }
        sum0 += __shfl_xor_sync(0xffffffffu, sum0, 1, 4);
        sum0 += __shfl_xor_sync(0xffffffffu, sum0, 2, 4);
        sum1 += __shfl_xor_sync(0xffffffffu, sum1, 1, 4);
        sum1 += __shfl_xor_sync(0xffffffffu, sum1, 2, 4);
        l0 = l0 * al0 + sum0;  m0 = mn0;
        l1 = l1 * al1 + sum1;  m1 = mn1;
#pragma unroll
        for (int nt = 0; nt < 8; ++nt) {
            oacc[nt][0] *= al0; oacc[nt][1] *= al0;
            oacc[nt][2] *= al1; oacc[nt][3] *= al1;
        }

        // ---- P fragments ----
        uint32_t aP[4][4];
#pragma unroll
        for (int j = 0; j < 4; ++j) {
            aP[j][0] = packh2(sacc[2 * j][0],     sacc[2 * j][1]);
            aP[j][1] = packh2(sacc[2 * j][2],     sacc[2 * j][3]);
            aP[j][2] = packh2(sacc[2 * j + 1][0], sacc[2 * j + 1][1]);
            aP[j][3] = packh2(sacc[2 * j + 1][2], sacc[2 * j + 1][3]);
        }

        // ---- O += P V (single pass) ----
#pragma unroll
        for (int p = 0; p < 4; ++p) {
#pragma unroll
            for (int j = 0; j < 4; ++j) {
                uint32_t vh[4];
                ldmx4t(vh, sb + FMAT + j * (16 * FROWB) + p * 32 + aLaneOff);
                mma16816(oacc[2 * p],     aP[j], vh);
                mma16816(oacc[2 * p + 1], aP[j], vh + 2);
            }
        }
        buf = (buf + 1 >= 3) ? 0 : buf + 1;
    }

    // ---- epilogue: normalize + fp16 store ----
    const float inv0 = 1.0f / l0, inv1 = 1.0f / l1;
    const size_t grow0 = (size_t)(b * Sq + qrow);
    const size_t grow1 = grow0 + 8;
#pragma unroll
    for (int nt = 0; nt < 8; ++nt) {
        const int col = h * HD + nt * 8 + (lane & 3) * 2;
        *(__half2*)(g_Oh + grow0 * Dm + col) =
            __floats2half2_rn(oacc[nt][0] * inv0, oacc[nt][1] * inv0);
        *(__half2*)(g_Oh + grow1 * Dm + col) =
            __floats2half2_rn(oacc[nt][2] * inv1, oacc[nt][3] * inv1);
    }
}

// ---------------------------------------------------------------------------
extern "C" void kernel_launch(void* const* d_in, const int* in_sizes, int n_in,
                              void* d_out, int out_size)
{
    const float* x   = (const float*)d_in[0];
    const float* Wq  = (const float*)d_in[1];
    const float* Wk  = (const float*)d_in[2];
    const float* Wv  = (const float*)d_in[3];
    const float* Wo  = (const float*)d_in[4];
    float*       out = (float*)d_out;

    cudaFuncSetAttribute(qkv_mma_kernel, cudaFuncAttributeMaxDynamicSharedMemorySize,
                         GEMM_SMEM);
    cudaFuncSetAttribute(oproj_mma_kernel, cudaFuncAttributeMaxDynamicSharedMemorySize,
                         GEMM_SMEM);
    cudaFuncSetAttribute(flash_mma_kernel, cudaFuncAttributeMaxDynamicSharedMemorySize,
                         FLASH_SMEM);

    // 0) RoPE cos/sin table
    init_cs_kernel<<<256, 256>>>();

    // 1) Convert X to fp16; transpose weights to fp16
    conv_x_kernel<<<(MT * Dm / 4 + 255) / 256, 256>>>(x, MT * Dm / 4);
    conv_wt_kernel<<<dim3(Dm / 32, Dm / 32, 4), dim3(32, 8)>>>(Wq, Wk, Wv, Wo);

    // 2) Q/K/V projections (HMMA fp16; Q rope+scale, K rope)
    qkv_mma_kernel<<<dim3(Dm / 128, MT / 128, 3), 256, GEMM_SMEM>>>();

    // 3) Causal flash attention on HMMA
    flash_mma_kernel<<<dim3(Sq / 128, Bc * Hh), 256, FLASH_SMEM>>>();

    // 4) Output projection (fp16 single pass, f32 out)
    oproj_mma_kernel<<<dim3(Dm / 128, MT / 128), 256, GEMM_SMEM>>>(out);
}

// round 15
// speedup vs baseline: 1.0116x; 1.0116x over previous
#include <cuda_runtime.h>
#include <cuda_fp16.h>
#include <math.h>
#include <stdint.h>

#define Bc 4
#define Sq 2048
#define Dm 1024
#define Hh 16
#define HD 64
#define MT (Bc*Sq)   // 8192 rows

#define QSCALE 0.18033688011112042f   // log2(e)/8  (scores in log2 domain)

// ---------------------------------------------------------------------------
// Static device scratch (allocation-guard safe).
// ---------------------------------------------------------------------------
__device__ __half g_Xhi[MT*Dm];                         // X (fp16)
__device__ __half g_Wth[4*Dm*Dm];                       // W^T (fp16, n-major)
__device__ __half g_Qh[MT*Dm];                          // rotated+scaled Q (fp16)
__device__ __half g_Kh[MT*Dm];                          // rotated K (fp16)
__device__ __half g_Vh[MT*Dm];                          // V (fp16)
__device__ __half g_Oh[MT*Dm];                          // attention output (fp16)
__device__ float2 g_cs[32*Sq];                          // [ip][pos] cos/sin

// ---------------------------------------------------------------------------
// PTX helpers (sm_80-era: cp.async, ldmatrix, mma.sync — valid on sm_103)
// ---------------------------------------------------------------------------
__device__ __forceinline__ uint32_t smem_u32(const void* p) {
    uint32_t a;
    asm("{ .reg .u64 t; cvta.to.shared.u64 t, %1; cvt.u32.u64 %0, t; }"
        : "=r"(a) : "l"(p));
    return a;
}
__device__ __forceinline__ void cp16(uint32_t dst, const void* src) {
    asm volatile("cp.async.cg.shared.global [%0], [%1], 16;" :: "r"(dst), "l"(src));
}
__device__ __forceinline__ void ldmx4(uint32_t* r, uint32_t addr) {
    asm volatile("ldmatrix.sync.aligned.m8n8.x4.shared.b16 {%0,%1,%2,%3}, [%4];"
                 : "=r"(r[0]), "=r"(r[1]), "=r"(r[2]), "=r"(r[3]) : "r"(addr));
}
__device__ __forceinline__ void ldmx4t(uint32_t* r, uint32_t addr) {
    asm volatile("ldmatrix.sync.aligned.m8n8.x4.trans.shared.b16 {%0,%1,%2,%3}, [%4];"
                 : "=r"(r[0]), "=r"(r[1]), "=r"(r[2]), "=r"(r[3]) : "r"(addr));
}
__device__ __forceinline__ void mma16816(float* c, const uint32_t* a, const uint32_t* b) {
    asm volatile("mma.sync.aligned.m16n8k16.row.col.f32.f16.f16.f32 "
                 "{%0,%1,%2,%3}, {%4,%5,%6,%7}, {%8,%9}, {%0,%1,%2,%3};"
                 : "+f"(c[0]), "+f"(c[1]), "+f"(c[2]), "+f"(c[3])
                 : "r"(a[0]), "r"(a[1]), "r"(a[2]), "r"(a[3]), "r"(b[0]), "r"(b[1]));
}
__device__ __forceinline__ uint32_t packh2(float a, float b) {
    __half2 h = __floats2half2_rn(a, b);
    return *(uint32_t*)&h;
}
// Fast 2^x on the FMA pipe (no MUFU). |err| ~2e-6 on the used range, x<=0.
__device__ __forceinline__ float exp2f_fast(float x) {
    x = fmaxf(x, -126.0f);
    float t  = x + 12582912.0f;              // round-to-nearest-int magic
    int   ei = __float_as_int(t) - 0x4B400000;
    float f  = x - (t - 12582912.0f);        // [-0.5, 0.5]
    float p  = 1.3333558146e-3f;
    p = fmaf(p, f, 9.6181291076e-3f);
    p = fmaf(p, f, 5.5504108665e-2f);
    p = fmaf(p, f, 2.4022650696e-1f);
    p = fmaf(p, f, 6.9314718056e-1f);
    p = fmaf(p, f, 1.0f);
    return __int_as_float(__float_as_int(p) + (ei << 23));
}

// ---------------------------------------------------------------------------
// Fused prep kernel: ONE launch does all three prep tasks concurrently.
//   blocks [0, 8192)            : X fp32 -> fp16         (conv_x)
//   blocks [8192, 8192+4096)    : W^T transpose+convert  (conv_wt)
//   blocks [12288, 12288+256)   : RoPE cos/sin table     (init_cs)
// ---------------------------------------------------------------------------
#define PREP_CONVX_BLOCKS 8192
#define PREP_WT_BLOCKS    4096
#define PREP_CS_BLOCKS    256
#define PREP_BLOCKS (PREP_CONVX_BLOCKS + PREP_WT_BLOCKS + PREP_CS_BLOCKS)

__global__ __launch_bounds__(256)
void prep_kernel(const float* __restrict__ x,
                 const float* __restrict__ Wq, const float* __restrict__ Wk,
                 const float* __restrict__ Wv, const float* __restrict__ Wo)
{
    __shared__ float ts[32][33];
    const int bid = blockIdx.x;
    const int tid = threadIdx.x;

    if (bid < PREP_CONVX_BLOCKS) {
        // --- conv_x: 8192 blocks x 256 threads x 4 floats = 8M elements
        int i = bid * 256 + tid;                 // float4 index
        float4 v = ((const float4*)x)[i];
        __half2* h2 = (__half2*)g_Xhi;
        h2[2 * i]     = __floats2half2_rn(v.x, v.y);
        h2[2 * i + 1] = __floats2half2_rn(v.z, v.w);
    } else if (bid < PREP_CONVX_BLOCKS + PREP_WT_BLOCKS) {
        // --- conv_wt: 4096 blocks = (32 x 32 tiles) x 4 matrices
        int wb = bid - PREP_CONVX_BLOCKS;
        int z  = wb >> 10;                       // 0..3
        int t2 = wb & 1023;
        int by = t2 >> 5, bx = t2 & 31;          // tile coords
        const float* W = (z == 0) ? Wq : (z == 1) ? Wk : (z == 2) ? Wv : Wo;
        int k0 = by * 32, n0 = bx * 32;
        int tx = tid & 31, ty = tid >> 5;        // 32 x 8
#pragma unroll
        for (int r = 0; r < 32; r += 8)
            ts[ty + r][tx] = W[(size_t)(k0 + ty + r) * Dm + n0 + tx];
        __syncthreads();
#pragma unroll
        for (int r = 0; r < 32; r += 8) {
            float v = ts[tx][ty + r];
            size_t o = (size_t)z * Dm * Dm + (size_t)(n0 + ty + r) * Dm + k0 + tx;
            g_Wth[o] = __float2half_rn(v);
        }
    } else {
        // --- init_cs: 256 blocks x 256 threads = 65536 entries
        int i  = (bid - PREP_CONVX_BLOCKS - PREP_WT_BLOCKS) * 256 + tid;
        int ip = i >> 11, pos = i & (Sq - 1);
        float invf = (float)exp(-(double)(2 * ip) * (log(10000.0) / 64.0));
        float sn, cn;
        sincosf((float)pos * invf, &sn, &cn);
        g_cs[i] = make_float2(cn, sn);
    }
}

// ---------------------------------------------------------------------------
// mma.sync fp16 GEMM: C = A * B^T (R13-measured-best mainloop: KC=32,
// ROWB=80, 2-stage cp.async, mid-chunk refill). CTA 128x128, 8 warps 64x32.
// Stage 20KB -> 40KB smem -> 2 CTAs/SM.
// MODE: 0 = f32 out (oproj); 1 = RoPE+scale fp16 out (Q);
//       2 = RoPE fp16 out (K); 3 = fp16 out (V)
// ---------------------------------------------------------------------------
#define KC 32
#define NCHUNK (Dm / KC)        // 32
#define ROWB 80
#define STG_MAT (128 * ROWB)    // 10240
#define STG_SIZE (2 * STG_MAT)  // 20480 : A, B
#define GEMM_SMEM (2 * STG_SIZE)  // 40960

__device__ __forceinline__ void load_chunk(uint32_t sb,
    const __half* __restrict__ A, const __half* __restrict__ B,
    int m0, int n0, int kc, int tid)
{
    const __half* srcs[2] = { A + (size_t)m0 * Dm + kc, B + (size_t)n0 * Dm + kc };
    const int row = (tid >> 2);
    const int s   = tid & 3;
#pragma unroll
    for (int j = 0; j < 4; ++j) {
        const int mat = j >> 1;
        const int r   = (j & 1) * 64 + row;
        cp16(sb + mat * STG_MAT + r * ROWB + s * 16,
             (const char*)(srcs[mat] + (size_t)r * Dm) + s * 16);
    }
}

__device__ __forceinline__ void gemm_frags(uint32_t aBase, uint32_t bBase, int s,
                                           uint32_t (*ah)[4], uint32_t (*bh)[2])
{
#pragma unroll
    for (int mt = 0; mt < 4; ++mt)
        ldmx4(ah[mt], aBase + mt * (16 * ROWB) + s * 32);
#pragma unroll
    for (int p = 0; p < 2; ++p) {
        uint32_t t[4];
        ldmx4(t, bBase + p * (16 * ROWB) + s * 32);
        bh[2 * p][0] = t[0]; bh[2 * p][1] = t[1];
        bh[2 * p + 1][0] = t[2]; bh[2 * p + 1][1] = t[3];
    }
}

__device__ __forceinline__ void gemm_mmas(float (*acc)[4][4],
                                          uint32_t (*ah)[4], uint32_t (*bh)[2])
{
#pragma unroll
    for (int mt = 0; mt < 4; ++mt)
#pragma unroll
        for (int nt = 0; nt < 4; ++nt)
            mma16816(acc[mt][nt], ah[mt], bh[nt]);
}

template <int MODE>
__device__ __forceinline__ void gemm_mma(const __half* __restrict__ A,
                                         const __half* __restrict__ B,
                                         float* __restrict__ Cf,
                                         __half* __restrict__ Ch)
{
    extern __shared__ char smraw[];
    const uint32_t sbase = smem_u32(smraw);

    const int tid  = threadIdx.x;
    const int wid  = tid >> 5, lane = tid & 31;
    const int wm   = wid & 1, wn = wid >> 1;
    const int m0   = blockIdx.y * 128, n0 = blockIdx.x * 128;

    const uint32_t aLaneOff = (lane & 15) * ROWB + (lane >> 4) * 16;
    const uint32_t bLaneOff = ((lane >> 4) * 8 + (lane & 7)) * ROWB + ((lane >> 3) & 1) * 16;

    float acc[4][4][4];
#pragma unroll
    for (int mt = 0; mt < 4; ++mt)
#pragma unroll
        for (int nt = 0; nt < 4; ++nt)
#pragma unroll
            for (int q = 0; q < 4; ++q) acc[mt][nt][q] = 0.0f;

#pragma unroll
    for (int c = 0; c < 2; ++c) {
        load_chunk(sbase + c * STG_SIZE, A, B, m0, n0, c * KC, tid);
        asm volatile("cp.async.commit_group;" ::: "memory");
    }

    for (int i = 0; i < NCHUNK; ++i) {
        asm volatile("cp.async.wait_group 1;" ::: "memory");
        __syncthreads();

        const uint32_t sb = sbase + (i & 1) * STG_SIZE;
        const uint32_t aBase = sb + (wm * 64) * ROWB + aLaneOff;
        const uint32_t bBase = sb + STG_MAT + (wn * 32) * ROWB + bLaneOff;

        // ---- k16 step 0: frags -> MMAs
        {
            uint32_t ah[4][4], bh[4][2];
            gemm_frags(aBase, bBase, 0, ah, bh);
            gemm_mmas(acc, ah, bh);
        }
        // ---- k16 step 1: frags -> barrier -> refill (overlaps MMAs) -> MMAs
        {
            uint32_t ah[4][4], bh[4][2];
            gemm_frags(aBase, bBase, 1, ah, bh);
            __syncthreads();   // all smem reads of this chunk complete
            if (i + 2 < NCHUNK)
                load_chunk(sbase + (i & 1) * STG_SIZE, A, B, m0, n0, (i + 2) * KC, tid);
            asm volatile("cp.async.commit_group;" ::: "memory");
            gemm_mmas(acc, ah, bh);
        }
    }

#pragma unroll
    for (int mt = 0; mt < 4; ++mt) {
        const int r = m0 + wm * 64 + mt * 16 + (lane >> 2);
#pragma unroll
        for (int nt = 0; nt < 4; ++nt) {
            const int c = n0 + wn * 32 + nt * 8 + (lane & 3) * 2;
            float v0 = acc[mt][nt][0], v1 = acc[mt][nt][1];
            float v2 = acc[mt][nt][2], v3 = acc[mt][nt][3];
            if (MODE == 1 || MODE == 2) {
                const int ip = (c & (HD - 1)) >> 1;
                float2 cs0 = g_cs[ip * Sq + (r & (Sq - 1))];
                float2 cs8 = g_cs[ip * Sq + ((r + 8) & (Sq - 1))];
                float t0 = v0 * cs0.x - v1 * cs0.y;
                float t1 = v0 * cs0.y + v1 * cs0.x;
                float t2 = v2 * cs8.x - v3 * cs8.y;
                float t3 = v2 * cs8.y + v3 * cs8.x;
                v0 = t0; v1 = t1; v2 = t2; v3 = t3;
            }
            if (MODE == 1) { v0 *= QSCALE; v1 *= QSCALE; v2 *= QSCALE; v3 *= QSCALE; }
            if (MODE == 0) {
                *(float2*)(Cf + (size_t)r * Dm + c)       = make_float2(v0, v1);
                *(float2*)(Cf + (size_t)(r + 8) * Dm + c) = make_float2(v2, v3);
            } else {
                *(__half2*)(Ch + (size_t)r * Dm + c)       = __floats2half2_rn(v0, v1);
                *(__half2*)(Ch + (size_t)(r + 8) * Dm + c) = __floats2half2_rn(v2, v3);
            }
        }
    }
}

__global__ __launch_bounds__(256, 2)
void qkv_mma_kernel() {
    const int z = blockIdx.z;
    const __half* Bh = g_Wth + (size_t)z * Dm * Dm;
    if (z == 0)      gemm_mma<1>(g_Xhi, Bh, nullptr, g_Qh);
    else if (z == 1) gemm_mma<2>(g_Xhi, Bh, nullptr, g_Kh);
    else             gemm_mma<3>(g_Xhi, Bh, nullptr, g_Vh);
}

__global__ __launch_bounds__(256, 2)
void oproj_mma_kernel(float* __restrict__ out) {
    gemm_mma<0>(g_Oh, g_Wth + (size_t)3 * Dm * Dm, out, nullptr);
}

// ---------------------------------------------------------------------------
// mma.sync flash attention (R13-measured-best). Br=128, Bk=64, hd=64.
// Single-pass QK and PV, log2-domain softmax, fp16 O, 2-stage KV ring.
// ---------------------------------------------------------------------------
#define FROWB 144                       // 64 halfs = 128B data + 16B pad
#define FQH_OFF 0
#define FST_OFF (128 * FROWB)           // 18432
#define FMAT (64 * FROWB)               // 9216
#define FST_SIZE (2 * FMAT)             // 18432 : Kh, Vh
#define FLASH_SMEM (FST_OFF + 2 * FST_SIZE)   // 55296

__device__ __forceinline__ void flash_load_kv(uint32_t sb, int kRow0, int h, int tid) {
    const __half* srcs[2] = { g_Kh, g_Vh };
#pragma unroll
    for (int j = 0; j < 4; ++j) {
        int it  = j * 256 + tid;          // 0..1023
        int mat = it >> 9;
        int row = (it >> 3) & 63;
        int seg = it & 7;
        cp16(sb + mat * FMAT + row * FROWB + seg * 16,
             srcs[mat] + (size_t)(kRow0 + row) * Dm + h * HD + seg * 8);
    }
}

__global__ __launch_bounds__(256, 2)
void flash_mma_kernel()
{
    extern __shared__ char smraw[];
    const uint32_t sbase = smem_u32(smraw);

    const int tid  = threadIdx.x;
    const int w    = tid >> 5, lane = tid & 31;
    const int bh   = blockIdx.y;
    const int b    = bh >> 4, h = bh & 15;
    const int qb   = gridDim.x - 1 - blockIdx.x;    // heavy blocks first
    const int q0   = qb * 128;
    const int qRow0 = b * Sq + q0;
    const int nkt  = 2 * qb + 2;

    const uint32_t aLaneOff = (lane & 15) * FROWB + (lane >> 4) * 16;
    const uint32_t bLaneOff = ((lane >> 4) * 8 + (lane & 7)) * FROWB + ((lane >> 3) & 1) * 16;

    // Q rows into smem (group 0, together with K/V tile 0)
#pragma unroll
    for (int j = 0; j < 4; ++j) {
        int it = j * 256 + tid;            // 0..1023
        int row = it >> 3, seg = it & 7;
        cp16(sbase + FQH_OFF + row * FROWB + seg * 16,
             g_Qh + (size_t)(qRow0 + row) * Dm + h * HD + seg * 8);
    }
    flash_load_kv(sbase + FST_OFF, b * Sq, h, tid);
    asm volatile("cp.async.commit_group;" ::: "memory");

    uint32_t qh[4][4];
    float oacc[8][4];
#pragma unroll
    for (int nt = 0; nt < 8; ++nt)
#pragma unroll
        for (int q = 0; q < 4; ++q) oacc[nt][q] = 0.0f;
    float m0 = -1e30f, m1 = -1e30f, l0 = 0.0f, l1 = 0.0f;
    const int qrow = q0 + w * 16 + (lane >> 2);   // seq pos of row r (r+8 = +8)

    for (int kt = 0; kt < nkt; ++kt) {
        if (kt + 1 < nkt)
            flash_load_kv(sbase + FST_OFF + ((kt + 1) & 1) * FST_SIZE,
                          b * Sq + (kt + 1) * 64, h, tid);
        asm volatile("cp.async.commit_group;" ::: "memory");
        asm volatile("cp.async.wait_group 1;" ::: "memory");
        __syncthreads();

        if (kt == 0) {   // Q fragments (Q arrived with group 0)
            const uint32_t qBaseH = sbase + FQH_OFF + (w * 16) * FROWB + aLaneOff;
#pragma unroll
            for (int j = 0; j < 4; ++j)
                ldmx4(qh[j], qBaseH + j * 32);
        }

        const uint32_t sb = sbase + FST_OFF + (kt & 1) * FST_SIZE;

        // ---- S = Q K^T (log2 units) ----
        float sacc[8][4];
#pragma unroll
        for (int nt = 0; nt < 8; ++nt)
#pragma unroll
            for (int q = 0; q < 4; ++q) sacc[nt][q] = 0.0f;

#pragma unroll
        for (int p = 0; p < 4; ++p) {
            const uint32_t kBase = sb + p * (16 * FROWB) + bLaneOff;
#pragma unroll
            for (int j = 0; j < 4; ++j) {
                uint32_t kh[4];
                ldmx4(kh, kBase + j * 32);
                mma16816(sacc[2 * p],     qh[j], kh);
                mma16816(sacc[2 * p + 1], qh[j], kh + 2);
            }
        }

        // ---- causal mask (diagonal-overlap tiles only) ----
        if (kt >= 2 * qb) {
#pragma unroll
            for (int nt = 0; nt < 8; ++nt) {
                const int col = kt * 64 + nt * 8 + (lane & 3) * 2;
                if (col     > qrow)     sacc[nt][0] = -1e30f;
                if (col + 1 > qrow)     sacc[nt][1] = -1e30f;
                if (col     > qrow + 8) sacc[nt][2] = -1e30f;
                if (col + 1 > qrow + 8) sacc[nt][3] = -1e30f;
            }
        }

        // ---- online softmax (quad-local reductions) ----
        float mx0 = -1e30f, mx1 = -1e30f;
#pragma unroll
        for (int nt = 0; nt < 8; ++nt) {
            mx0 = fmaxf(mx0, fmaxf(sacc[nt][0], sacc[nt][1]));
            mx1 = fmaxf(mx1, fmaxf(sacc[nt][2], sacc[nt][3]));
        }
        mx0 = fmaxf(mx0, __shfl_xor_sync(0xffffffffu, mx0, 1, 4));
        mx0 = fmaxf(mx0, __shfl_xor_sync(0xffffffffu, mx0, 2, 4));
        mx1 = fmaxf(mx1, __shfl_xor_sync(0xffffffffu, mx1, 1, 4));
        mx1 = fmaxf(mx1, __shfl_xor_sync(0xffffffffu, mx1, 2, 4));
        const float mn0 = fmaxf(m0, mx0), mn1 = fmaxf(m1, mx1);
        const float al0 = exp2f_fast(m0 - mn0), al1 = exp2f_fast(m1 - mn1);
        float sum0 = 0.0f, sum1 = 0.0f;
#pragma unroll
        for (int nt = 0; nt < 8; ++nt) {
            sacc[nt][0] = exp2f_fast(sacc[nt][0] - mn0);
            sacc[nt][1] = exp2f_fast(sacc[nt][1] - mn0);
            sacc[nt][2] = exp2f_fast(sacc[nt][2] - mn1);
            sacc[nt][3] = exp2f_fast(sacc[nt][3] - mn1);
            sum0 += sacc[nt][0] + sacc[nt][1];
            sum1 += sacc[nt][2] + sacc[nt][3];
        }
        sum0 += __shfl_xor_sync(0xffffffffu, sum0, 1, 4);
        sum0 += __shfl_xor_sync(0xffffffffu, sum0, 2, 4);
        sum1 += __shfl_xor_sync(0xffffffffu, sum1, 1, 4);
        sum1 += __shfl_xor_sync(0xffffffffu, sum1, 2, 4);
        l0 = l0 * al0 + sum0;  m0 = mn0;
        l1 = l1 * al1 + sum1;  m1 = mn1;
#pragma unroll
        for (int nt = 0; nt < 8; ++nt) {
            oacc[nt][0] *= al0; oacc[nt][1] *= al0;
            oacc[nt][2] *= al1; oacc[nt][3] *= al1;
        }

        // ---- P fragments ----
        uint32_t aP[4][4];
#pragma unroll
        for (int j = 0; j < 4; ++j) {
            aP[j][0] = packh2(sacc[2 * j][0],     sacc[2 * j][1]);
            aP[j][1] = packh2(sacc[2 * j][2],     sacc[2 * j][3]);
            aP[j][2] = packh2(sacc[2 * j + 1][0], sacc[2 * j + 1][1]);
            aP[j][3] = packh2(sacc[2 * j + 1][2], sacc[2 * j + 1][3]);
        }

        // ---- O += P V (single pass) ----
#pragma unroll
        for (int p = 0; p < 4; ++p) {
#pragma unroll
            for (int j = 0; j < 4; ++j) {
                uint32_t vh[4];
                ldmx4t(vh, sb + FMAT + j * (16 * FROWB) + p * 32 + aLaneOff);
                mma16816(oacc[2 * p],     aP[j], vh);
                mma16816(oacc[2 * p + 1], aP[j], vh + 2);
            }
        }
        __syncthreads();
    }

    // ---- epilogue: normalize + fp16 store ----
    const float inv0 = 1.0f / l0, inv1 = 1.0f / l1;
    const size_t grow0 = (size_t)(b * Sq + qrow);
    const size_t grow1 = grow0 + 8;
#pragma unroll
    for (int nt = 0; nt < 8; ++nt) {
        const int col = h * HD + nt * 8 + (lane & 3) * 2;
        *(__half2*)(g_Oh + grow0 * Dm + col) =
            __floats2half2_rn(oacc[nt][0] * inv0, oacc[nt][1] * inv0);
        *(__half2*)(g_Oh + grow1 * Dm + col) =
            __floats2half2_rn(oacc[nt][2] * inv1, oacc[nt][3] * inv1);
    }
}

// ---------------------------------------------------------------------------
extern "C" void kernel_launch(void* const* d_in, const int* in_sizes, int n_in,
                              void* d_out, int out_size)
{
    const float* x   = (const float*)d_in[0];
    const float* Wq  = (const float*)d_in[1];
    const float* Wk  = (const float*)d_in[2];
    const float* Wv  = (const float*)d_in[3];
    const float* Wo  = (const float*)d_in[4];
    float*       out = (float*)d_out;

    cudaFuncSetAttribute(qkv_mma_kernel, cudaFuncAttributeMaxDynamicSharedMemorySize,
                         GEMM_SMEM);
    cudaFuncSetAttribute(oproj_mma_kernel, cudaFuncAttributeMaxDynamicSharedMemorySize,
                         GEMM_SMEM);
    cudaFuncSetAttribute(flash_mma_kernel, cudaFuncAttributeMaxDynamicSharedMemorySize,
                         FLASH_SMEM);

    // 1) Fused prep: X->fp16, W^T->fp16, RoPE table — one launch
    prep_kernel<<<PREP_BLOCKS, 256>>>(x, Wq, Wk, Wv, Wo);

    // 2) Q/K/V projections (HMMA fp16; Q rope+scale, K rope)
    qkv_mma_kernel<<<dim3(Dm / 128, MT / 128, 3), 256, GEMM_SMEM>>>();

    // 3) Causal flash attention on HMMA
    flash_mma_kernel<<<dim3(Sq / 128, Bc * Hh), 256, FLASH_SMEM>>>();

    // 4) Output projection (fp16 single pass, f32 out)
    oproj_mma_kernel<<<dim3(Dm / 128, MT / 128), 256, GEMM_SMEM>>>(out);
}

// round 16
// speedup vs baseline: 1.1193x; 1.1065x over previous
#include <cuda_runtime.h>
#include <cuda_fp16.h>
#include <math.h>
#include <stdint.h>

#define Bc 4
#define Sq 2048
#define Dm 1024
#define Hh 16
#define HD 64
#define MT (Bc*Sq)   // 8192 rows

#define QSCALE 0.18033688011112042f   // log2(e)/8  (scores in log2 domain)

// ---------------------------------------------------------------------------
// Static device scratch (allocation-guard safe).
// ---------------------------------------------------------------------------
__device__ __half g_Xhi[MT*Dm];                         // X (fp16)
__device__ __half g_Wth[4*Dm*Dm];                       // W^T (fp16, n-major)
__device__ __half g_Qh[MT*Dm];                          // rotated+scaled Q (fp16)
__device__ __half g_Kh[MT*Dm];                          // rotated K (fp16)
__device__ __half g_Vh[MT*Dm];                          // V (fp16)
__device__ __half g_Oh[MT*Dm];                          // attention output (fp16)
__device__ float2 g_cs[32*Sq];                          // [ip][pos] cos/sin

// ---------------------------------------------------------------------------
// PTX helpers (sm_80-era: cp.async, ldmatrix, mma.sync — valid on sm_103)
// ---------------------------------------------------------------------------
__device__ __forceinline__ uint32_t smem_u32(const void* p) {
    uint32_t a;
    asm("{ .reg .u64 t; cvta.to.shared.u64 t, %1; cvt.u32.u64 %0, t; }"
        : "=r"(a) : "l"(p));
    return a;
}
__device__ __forceinline__ void cp16(uint32_t dst, const void* src) {
    asm volatile("cp.async.cg.shared.global [%0], [%1], 16;" :: "r"(dst), "l"(src));
}
__device__ __forceinline__ void ldmx4(uint32_t* r, uint32_t addr) {
    asm volatile("ldmatrix.sync.aligned.m8n8.x4.shared.b16 {%0,%1,%2,%3}, [%4];"
                 : "=r"(r[0]), "=r"(r[1]), "=r"(r[2]), "=r"(r[3]) : "r"(addr));
}
__device__ __forceinline__ void ldmx4t(uint32_t* r, uint32_t addr) {
    asm volatile("ldmatrix.sync.aligned.m8n8.x4.trans.shared.b16 {%0,%1,%2,%3}, [%4];"
                 : "=r"(r[0]), "=r"(r[1]), "=r"(r[2]), "=r"(r[3]) : "r"(addr));
}
__device__ __forceinline__ void mma16816(float* c, const uint32_t* a, const uint32_t* b) {
    asm volatile("mma.sync.aligned.m16n8k16.row.col.f32.f16.f16.f32 "
                 "{%0,%1,%2,%3}, {%4,%5,%6,%7}, {%8,%9}, {%0,%1,%2,%3};"
                 : "+f"(c[0]), "+f"(c[1]), "+f"(c[2]), "+f"(c[3])
                 : "r"(a[0]), "r"(a[1]), "r"(a[2]), "r"(a[3]), "r"(b[0]), "r"(b[1]));
}
__device__ __forceinline__ uint32_t packh2(float a, float b) {
    __half2 h = __floats2half2_rn(a, b);
    return *(uint32_t*)&h;
}
// MUFU 2^x — 1 issue slot instead of ~9 FMA slots; |rel err| ~2^-22.
// Returns 0 for very negative x (exactly what masked scores need).
__device__ __forceinline__ float ex2f(float x) {
    float y;
    asm("ex2.approx.f32 %0, %1;" : "=f"(y) : "f"(x));
    return y;
}

// ---------------------------------------------------------------------------
// Fused prep kernel: ONE launch does all three prep tasks concurrently.
//   blocks [0, 8192)            : X fp32 -> fp16         (conv_x)
//   blocks [8192, 8192+4096)    : W^T transpose+convert  (conv_wt)
//   blocks [12288, 12288+256)   : RoPE cos/sin table     (init_cs)
// ---------------------------------------------------------------------------
#define PREP_CONVX_BLOCKS 8192
#define PREP_WT_BLOCKS    4096
#define PREP_CS_BLOCKS    256
#define PREP_BLOCKS (PREP_CONVX_BLOCKS + PREP_WT_BLOCKS + PREP_CS_BLOCKS)

__global__ __launch_bounds__(256)
void prep_kernel(const float* __restrict__ x,
                 const float* __restrict__ Wq, const float* __restrict__ Wk,
                 const float* __restrict__ Wv, const float* __restrict__ Wo)
{
    __shared__ float ts[32][33];
    const int bid = blockIdx.x;
    const int tid = threadIdx.x;

    if (bid < PREP_CONVX_BLOCKS) {
        int i = bid * 256 + tid;                 // float4 index
        float4 v = ((const float4*)x)[i];
        __half2* h2 = (__half2*)g_Xhi;
        h2[2 * i]     = __floats2half2_rn(v.x, v.y);
        h2[2 * i + 1] = __floats2half2_rn(v.z, v.w);
    } else if (bid < PREP_CONVX_BLOCKS + PREP_WT_BLOCKS) {
        int wb = bid - PREP_CONVX_BLOCKS;
        int z  = wb >> 10;                       // 0..3
        int t2 = wb & 1023;
        int by = t2 >> 5, bx = t2 & 31;
        const float* W = (z == 0) ? Wq : (z == 1) ? Wk : (z == 2) ? Wv : Wo;
        int k0 = by * 32, n0 = bx * 32;
        int tx = tid & 31, ty = tid >> 5;
#pragma unroll
        for (int r = 0; r < 32; r += 8)
            ts[ty + r][tx] = W[(size_t)(k0 + ty + r) * Dm + n0 + tx];
        __syncthreads();
#pragma unroll
        for (int r = 0; r < 32; r += 8) {
            float v = ts[tx][ty + r];
            size_t o = (size_t)z * Dm * Dm + (size_t)(n0 + ty + r) * Dm + k0 + tx;
            g_Wth[o] = __float2half_rn(v);
        }
    } else {
        int i  = (bid - PREP_CONVX_BLOCKS - PREP_WT_BLOCKS) * 256 + tid;
        int ip = i >> 11, pos = i & (Sq - 1);
        float invf = (float)exp(-(double)(2 * ip) * (log(10000.0) / 64.0));
        float sn, cn;
        sincosf((float)pos * invf, &sn, &cn);
        g_cs[i] = make_float2(cn, sn);
    }
}

// ---------------------------------------------------------------------------
// mma.sync fp16 GEMM: C = A * B^T (R13-measured-best mainloop: KC=32,
// ROWB=80, 2-stage cp.async, mid-chunk refill). CTA 128x128, 8 warps 64x32.
// Stage 20KB -> 40KB smem -> 2 CTAs/SM.  [FROZEN — local optimum]
// MODE: 0 = f32 out (oproj); 1 = RoPE+scale fp16 out (Q);
//       2 = RoPE fp16 out (K); 3 = fp16 out (V)
// ---------------------------------------------------------------------------
#define KC 32
#define NCHUNK (Dm / KC)        // 32
#define ROWB 80
#define STG_MAT (128 * ROWB)    // 10240
#define STG_SIZE (2 * STG_MAT)  // 20480 : A, B
#define GEMM_SMEM (2 * STG_SIZE)  // 40960

__device__ __forceinline__ void load_chunk(uint32_t sb,
    const __half* __restrict__ A, const __half* __restrict__ B,
    int m0, int n0, int kc, int tid)
{
    const __half* srcs[2] = { A + (size_t)m0 * Dm + kc, B + (size_t)n0 * Dm + kc };
    const int row = (tid >> 2);
    const int s   = tid & 3;
#pragma unroll
    for (int j = 0; j < 4; ++j) {
        const int mat = j >> 1;
        const int r   = (j & 1) * 64 + row;
        cp16(sb + mat * STG_MAT + r * ROWB + s * 16,
             (const char*)(srcs[mat] + (size_t)r * Dm) + s * 16);
    }
}

__device__ __forceinline__ void gemm_frags(uint32_t aBase, uint32_t bBase, int s,
                                           uint32_t (*ah)[4], uint32_t (*bh)[2])
{
#pragma unroll
    for (int mt = 0; mt < 4; ++mt)
        ldmx4(ah[mt], aBase + mt * (16 * ROWB) + s * 32);
#pragma unroll
    for (int p = 0; p < 2; ++p) {
        uint32_t t[4];
        ldmx4(t, bBase + p * (16 * ROWB) + s * 32);
        bh[2 * p][0] = t[0]; bh[2 * p][1] = t[1];
        bh[2 * p + 1][0] = t[2]; bh[2 * p + 1][1] = t[3];
    }
}

__device__ __forceinline__ void gemm_mmas(float (*acc)[4][4],
                                          uint32_t (*ah)[4], uint32_t (*bh)[2])
{
#pragma unroll
    for (int mt = 0; mt < 4; ++mt)
#pragma unroll
        for (int nt = 0; nt < 4; ++nt)
            mma16816(acc[mt][nt], ah[mt], bh[nt]);
}

template <int MODE>
__device__ __forceinline__ void gemm_mma(const __half* __restrict__ A,
                                         const __half* __restrict__ B,
                                         float* __restrict__ Cf,
                                         __half* __restrict__ Ch)
{
    extern __shared__ char smraw[];
    const uint32_t sbase = smem_u32(smraw);

    const int tid  = threadIdx.x;
    const int wid  = tid >> 5, lane = tid & 31;
    const int wm   = wid & 1, wn = wid >> 1;
    const int m0   = blockIdx.y * 128, n0 = blockIdx.x * 128;

    const uint32_t aLaneOff = (lane & 15) * ROWB + (lane >> 4) * 16;
    const uint32_t bLaneOff = ((lane >> 4) * 8 + (lane & 7)) * ROWB + ((lane >> 3) & 1) * 16;

    float acc[4][4][4];
#pragma unroll
    for (int mt = 0; mt < 4; ++mt)
#pragma unroll
        for (int nt = 0; nt < 4; ++nt)
#pragma unroll
            for (int q = 0; q < 4; ++q) acc[mt][nt][q] = 0.0f;

#pragma unroll
    for (int c = 0; c < 2; ++c) {
        load_chunk(sbase + c * STG_SIZE, A, B, m0, n0, c * KC, tid);
        asm volatile("cp.async.commit_group;" ::: "memory");
    }

    for (int i = 0; i < NCHUNK; ++i) {
        asm volatile("cp.async.wait_group 1;" ::: "memory");
        __syncthreads();

        const uint32_t sb = sbase + (i & 1) * STG_SIZE;
        const uint32_t aBase = sb + (wm * 64) * ROWB + aLaneOff;
        const uint32_t bBase = sb + STG_MAT + (wn * 32) * ROWB + bLaneOff;

        // ---- k16 step 0: frags -> MMAs
        {
            uint32_t ah[4][4], bh[4][2];
            gemm_frags(aBase, bBase, 0, ah, bh);
            gemm_mmas(acc, ah, bh);
        }
        // ---- k16 step 1: frags -> barrier -> refill (overlaps MMAs) -> MMAs
        {
            uint32_t ah[4][4], bh[4][2];
            gemm_frags(aBase, bBase, 1, ah, bh);
            __syncthreads();   // all smem reads of this chunk complete
            if (i + 2 < NCHUNK)
                load_chunk(sbase + (i & 1) * STG_SIZE, A, B, m0, n0, (i + 2) * KC, tid);
            asm volatile("cp.async.commit_group;" ::: "memory");
            gemm_mmas(acc, ah, bh);
        }
    }

#pragma unroll
    for (int mt = 0; mt < 4; ++mt) {
        const int r = m0 + wm * 64 + mt * 16 + (lane >> 2);
#pragma unroll
        for (int nt = 0; nt < 4; ++nt) {
            const int c = n0 + wn * 32 + nt * 8 + (lane & 3) * 2;
            float v0 = acc[mt][nt][0], v1 = acc[mt][nt][1];
            float v2 = acc[mt][nt][2], v3 = acc[mt][nt][3];
            if (MODE == 1 || MODE == 2) {
                const int ip = (c & (HD - 1)) >> 1;
                float2 cs0 = g_cs[ip * Sq + (r & (Sq - 1))];
                float2 cs8 = g_cs[ip * Sq + ((r + 8) & (Sq - 1))];
                float t0 = v0 * cs0.x - v1 * cs0.y;
                float t1 = v0 * cs0.y + v1 * cs0.x;
                float t2 = v2 * cs8.x - v3 * cs8.y;
                float t3 = v2 * cs8.y + v3 * cs8.x;
                v0 = t0; v1 = t1; v2 = t2; v3 = t3;
            }
            if (MODE == 1) { v0 *= QSCALE; v1 *= QSCALE; v2 *= QSCALE; v3 *= QSCALE; }
            if (MODE == 0) {
                *(float2*)(Cf + (size_t)r * Dm + c)       = make_float2(v0, v1);
                *(float2*)(Cf + (size_t)(r + 8) * Dm + c) = make_float2(v2, v3);
            } else {
                *(__half2*)(Ch + (size_t)r * Dm + c)       = __floats2half2_rn(v0, v1);
                *(__half2*)(Ch + (size_t)(r + 8) * Dm + c) = __floats2half2_rn(v2, v3);
            }
        }
    }
}

__global__ __launch_bounds__(256, 2)
void qkv_mma_kernel() {
    const int z = blockIdx.z;
    const __half* Bh = g_Wth + (size_t)z * Dm * Dm;
    if (z == 0)      gemm_mma<1>(g_Xhi, Bh, nullptr, g_Qh);
    else if (z == 1) gemm_mma<2>(g_Xhi, Bh, nullptr, g_Kh);
    else             gemm_mma<3>(g_Xhi, Bh, nullptr, g_Vh);
}

__global__ __launch_bounds__(256, 2)
void oproj_mma_kernel(float* __restrict__ out) {
    gemm_mma<0>(g_Oh, g_Wth + (size_t)3 * Dm * Dm, out, nullptr);
}

// ---------------------------------------------------------------------------
// mma.sync flash attention. Br=128, Bk=64, hd=64. Single-pass QK and PV,
// log2-domain softmax with MUFU ex2 (1 issue slot/exp) and DEFERRED row-sum
// (lane-local l partials; quad-reduce once in the epilogue). fp16 O output.
// ---------------------------------------------------------------------------
#define FROWB 144                       // 64 halfs = 128B data + 16B pad
#define FQH_OFF 0
#define FST_OFF (128 * FROWB)           // 18432
#define FMAT (64 * FROWB)               // 9216
#define FST_SIZE (2 * FMAT)             // 18432 : Kh, Vh
#define FLASH_SMEM (FST_OFF + 2 * FST_SIZE)   // 55296

__device__ __forceinline__ void flash_load_kv(uint32_t sb, int kRow0, int h, int tid) {
    const __half* srcs[2] = { g_Kh, g_Vh };
#pragma unroll
    for (int j = 0; j < 4; ++j) {
        int it  = j * 256 + tid;          // 0..1023
        int mat = it >> 9;
        int row = (it >> 3) & 63;
        int seg = it & 7;
        cp16(sb + mat * FMAT + row * FROWB + seg * 16,
             srcs[mat] + (size_t)(kRow0 + row) * Dm + h * HD + seg * 8);
    }
}

__global__ __launch_bounds__(256, 2)
void flash_mma_kernel()
{
    extern __shared__ char smraw[];
    const uint32_t sbase = smem_u32(smraw);

    const int tid  = threadIdx.x;
    const int w    = tid >> 5, lane = tid & 31;
    const int bh   = blockIdx.y;
    const int b    = bh >> 4, h = bh & 15;
    const int qb   = gridDim.x - 1 - blockIdx.x;    // heavy blocks first
    const int q0   = qb * 128;
    const int qRow0 = b * Sq + q0;
    const int nkt  = 2 * qb + 2;

    const uint32_t aLaneOff = (lane & 15) * FROWB + (lane >> 4) * 16;
    const uint32_t bLaneOff = ((lane >> 4) * 8 + (lane & 7)) * FROWB + ((lane >> 3) & 1) * 16;

    // Q rows into smem (group 0, together with K/V tile 0)
#pragma unroll
    for (int j = 0; j < 4; ++j) {
        int it = j * 256 + tid;            // 0..1023
        int row = it >> 3, seg = it & 7;
        cp16(sbase + FQH_OFF + row * FROWB + seg * 16,
             g_Qh + (size_t)(qRow0 + row) * Dm + h * HD + seg * 8);
    }
    flash_load_kv(sbase + FST_OFF, b * Sq, h, tid);
    asm volatile("cp.async.commit_group;" ::: "memory");

    uint32_t qh[4][4];
    float oacc[8][4];
#pragma unroll
    for (int nt = 0; nt < 8; ++nt)
#pragma unroll
        for (int q = 0; q < 4; ++q) oacc[nt][q] = 0.0f;
    float m0 = -1e30f, m1 = -1e30f;
    float l0 = 0.0f, l1 = 0.0f;       // LANE-LOCAL partials (quad-reduced at end)
    const int qrow = q0 + w * 16 + (lane >> 2);   // seq pos of row r (r+8 = +8)

    for (int kt = 0; kt < nkt; ++kt) {
        if (kt + 1 < nkt)
            flash_load_kv(sbase + FST_OFF + ((kt + 1) & 1) * FST_SIZE,
                          b * Sq + (kt + 1) * 64, h, tid);
        asm volatile("cp.async.commit_group;" ::: "memory");
        asm volatile("cp.async.wait_group 1;" ::: "memory");
        __syncthreads();

        if (kt == 0) {   // Q fragments (Q arrived with group 0)
            const uint32_t qBaseH = sbase + FQH_OFF + (w * 16) * FROWB + aLaneOff;
#pragma unroll
            for (int j = 0; j < 4; ++j)
                ldmx4(qh[j], qBaseH + j * 32);
        }

        const uint32_t sb = sbase + FST_OFF + (kt & 1) * FST_SIZE;

        // ---- S = Q K^T (log2 units) ----
        float sacc[8][4];
#pragma unroll
        for (int nt = 0; nt < 8; ++nt)
#pragma unroll
            for (int q = 0; q < 4; ++q) sacc[nt][q] = 0.0f;

#pragma unroll
        for (int p = 0; p < 4; ++p) {
            const uint32_t kBase = sb + p * (16 * FROWB) + bLaneOff;
#pragma unroll
            for (int j = 0; j < 4; ++j) {
                uint32_t kh[4];
                ldmx4(kh, kBase + j * 32);
                mma16816(sacc[2 * p],     qh[j], kh);
                mma16816(sacc[2 * p + 1], qh[j], kh + 2);
            }
        }

        // ---- causal mask (diagonal-overlap tiles only) ----
        if (kt >= 2 * qb) {
#pragma unroll
            for (int nt = 0; nt < 8; ++nt) {
                const int col = kt * 64 + nt * 8 + (lane & 3) * 2;
                if (col     > qrow)     sacc[nt][0] = -1e30f;
                if (col + 1 > qrow)     sacc[nt][1] = -1e30f;
                if (col     > qrow + 8) sacc[nt][2] = -1e30f;
                if (col + 1 > qrow + 8) sacc[nt][3] = -1e30f;
            }
        }

        // ---- online softmax: quad-global max, lane-local sums ----
        float mx0 = -1e30f, mx1 = -1e30f;
#pragma unroll
        for (int nt = 0; nt < 8; ++nt) {
            mx0 = fmaxf(mx0, fmaxf(sacc[nt][0], sacc[nt][1]));
            mx1 = fmaxf(mx1, fmaxf(sacc[nt][2], sacc[nt][3]));
        }
        mx0 = fmaxf(mx0, __shfl_xor_sync(0xffffffffu, mx0, 1, 4));
        mx0 = fmaxf(mx0, __shfl_xor_sync(0xffffffffu, mx0, 2, 4));
        mx1 = fmaxf(mx1, __shfl_xor_sync(0xffffffffu, mx1, 1, 4));
        mx1 = fmaxf(mx1, __shfl_xor_sync(0xffffffffu, mx1, 2, 4));
        const float mn0 = fmaxf(m0, mx0), mn1 = fmaxf(m1, mx1);
        const float al0 = ex2f(m0 - mn0), al1 = ex2f(m1 - mn1);
        float sum0 = 0.0f, sum1 = 0.0f;
#pragma unroll
        for (int nt = 0; nt < 8; ++nt) {
            sacc[nt][0] = ex2f(sacc[nt][0] - mn0);
            sacc[nt][1] = ex2f(sacc[nt][1] - mn0);
            sacc[nt][2] = ex2f(sacc[nt][2] - mn1);
            sacc[nt][3] = ex2f(sacc[nt][3] - mn1);
            sum0 += sacc[nt][0] + sacc[nt][1];
            sum1 += sacc[nt][2] + sacc[nt][3];
        }
        l0 = l0 * al0 + sum0;  m0 = mn0;   // lane-local partial of the row sum
        l1 = l1 * al1 + sum1;  m1 = mn1;
#pragma unroll
        for (int nt = 0; nt < 8; ++nt) {
            oacc[nt][0] *= al0; oacc[nt][1] *= al0;
            oacc[nt][2] *= al1; oacc[nt][3] *= al1;
        }

        // ---- P fragments ----
        uint32_t aP[4][4];
#pragma unroll
        for (int j = 0; j < 4; ++j) {
            aP[j][0] = packh2(sacc[2 * j][0],     sacc[2 * j][1]);
            aP[j][1] = packh2(sacc[2 * j][2],     sacc[2 * j][3]);
            aP[j][2] = packh2(sacc[2 * j + 1][0], sacc[2 * j + 1][1]);
            aP[j][3] = packh2(sacc[2 * j + 1][2], sacc[2 * j + 1][3]);
        }

        // ---- O += P V (single pass) ----
#pragma unroll
        for (int p = 0; p < 4; ++p) {
#pragma unroll
            for (int j = 0; j < 4; ++j) {
                uint32_t vh[4];
                ldmx4t(vh, sb + FMAT + j * (16 * FROWB) + p * 32 + aLaneOff);
                mma16816(oacc[2 * p],     aP[j], vh);
                mma16816(oacc[2 * p + 1], aP[j], vh + 2);
            }
        }
        __syncthreads();
    }

    // ---- epilogue: quad-reduce l, normalize, fp16 store ----
    l0 += __shfl_xor_sync(0xffffffffu, l0, 1, 4);
    l0 += __shfl_xor_sync(0xffffffffu, l0, 2, 4);
    l1 += __shfl_xor_sync(0xffffffffu, l1, 1, 4);
    l1 += __shfl_xor_sync(0xffffffffu, l1, 2, 4);
    const float inv0 = 1.0f / l0, inv1 = 1.0f / l1;
    const size_t grow0 = (size_t)(b * Sq + qrow);
    const size_t grow1 = grow0 + 8;
#pragma unroll
    for (int nt = 0; nt < 8; ++nt) {
        const int col = h * HD + nt * 8 + (lane & 3) * 2;
        *(__half2*)(g_Oh + grow0 * Dm + col) =
            __floats2half2_rn(oacc[nt][0] * inv0, oacc[nt][1] * inv0);
        *(__half2*)(g_Oh + grow1 * Dm + col) =
            __floats2half2_rn(oacc[nt][2] * inv1, oacc[nt][3] * inv1);
    }
}

// ---------------------------------------------------------------------------
extern "C" void kernel_launch(void* const* d_in, const int* in_sizes, int n_in,
                              void* d_out, int out_size)
{
    const float* x   = (const float*)d_in[0];
    const float* Wq  = (const float*)d_in[1];
    const float* Wk  = (const float*)d_in[2];
    const float* Wv  = (const float*)d_in[3];
    const float* Wo  = (const float*)d_in[4];
    float*       out = (float*)d_out;

    cudaFuncSetAttribute(qkv_mma_kernel, cudaFuncAttributeMaxDynamicSharedMemorySize,
                         GEMM_SMEM);
    cudaFuncSetAttribute(oproj_mma_kernel, cudaFuncAttributeMaxDynamicSharedMemorySize,
                         GEMM_SMEM);
    cudaFuncSetAttribute(flash_mma_kernel, cudaFuncAttributeMaxDynamicSharedMemorySize,
                         FLASH_SMEM);

    // 1) Fused prep: X->fp16, W^T->fp16, RoPE table — one launch
    prep_kernel<<<PREP_BLOCKS, 256>>>(x, Wq, Wk, Wv, Wo);

    // 2) Q/K/V projections (HMMA fp16; Q rope+scale, K rope)
    qkv_mma_kernel<<<dim3(Dm / 128, MT / 128, 3), 256, GEMM_SMEM>>>();

    // 3) Causal flash attention on HMMA
    flash_mma_kernel<<<dim3(Sq / 128, Bc * Hh), 256, FLASH_SMEM>>>();

    // 4) Output projection (fp16 single pass, f32 out)
    oproj_mma_kernel<<<dim3(Dm / 128, MT / 128), 256, GEMM_SMEM>>>(out);
}

// round 17
// speedup vs baseline: 1.1440x; 1.0221x over previous
#include <cuda_runtime.h>
#include <cuda_fp16.h>
#include <math.h>
#include <stdint.h>

#define Bc 4
#define Sq 2048
#define Dm 1024
#define Hh 16
#define HD 64
#define MT (Bc*Sq)   // 8192 rows

#define QSCALE 0.18033688011112042f   // log2(e)/8  (scores in log2 domain)

// ---------------------------------------------------------------------------
// Static device scratch (allocation-guard safe).
// ---------------------------------------------------------------------------
__device__ __half g_Xhi[MT*Dm];                         // X (fp16)
__device__ __half g_Wth[4*Dm*Dm];                       // W^T (fp16, n-major)
__device__ __half g_Qh[MT*Dm];                          // rotated+scaled Q (fp16)
__device__ __half g_Kh[MT*Dm];                          // rotated K (fp16)
__device__ __half g_Vh[MT*Dm];                          // V (fp16)
__device__ __half g_Oh[MT*Dm];                          // attention output (fp16)
__device__ float2 g_cs[32*Sq];                          // [ip][pos] cos/sin

// ---------------------------------------------------------------------------
// PTX helpers (sm_80-era: cp.async, ldmatrix, mma.sync — valid on sm_103)
// ---------------------------------------------------------------------------
__device__ __forceinline__ uint32_t smem_u32(const void* p) {
    uint32_t a;
    asm("{ .reg .u64 t; cvta.to.shared.u64 t, %1; cvt.u32.u64 %0, t; }"
        : "=r"(a) : "l"(p));
    return a;
}
__device__ __forceinline__ void cp16(uint32_t dst, const void* src) {
    asm volatile("cp.async.cg.shared.global [%0], [%1], 16;" :: "r"(dst), "l"(src));
}
__device__ __forceinline__ void ldmx4(uint32_t* r, uint32_t addr) {
    asm volatile("ldmatrix.sync.aligned.m8n8.x4.shared.b16 {%0,%1,%2,%3}, [%4];"
                 : "=r"(r[0]), "=r"(r[1]), "=r"(r[2]), "=r"(r[3]) : "r"(addr));
}
__device__ __forceinline__ void ldmx4t(uint32_t* r, uint32_t addr) {
    asm volatile("ldmatrix.sync.aligned.m8n8.x4.trans.shared.b16 {%0,%1,%2,%3}, [%4];"
                 : "=r"(r[0]), "=r"(r[1]), "=r"(r[2]), "=r"(r[3]) : "r"(addr));
}
__device__ __forceinline__ void mma16816(float* c, const uint32_t* a, const uint32_t* b) {
    asm volatile("mma.sync.aligned.m16n8k16.row.col.f32.f16.f16.f32 "
                 "{%0,%1,%2,%3}, {%4,%5,%6,%7}, {%8,%9}, {%0,%1,%2,%3};"
                 : "+f"(c[0]), "+f"(c[1]), "+f"(c[2]), "+f"(c[3])
                 : "r"(a[0]), "r"(a[1]), "r"(a[2]), "r"(a[3]), "r"(b[0]), "r"(b[1]));
}
__device__ __forceinline__ uint32_t packh2(float a, float b) {
    __half2 h = __floats2half2_rn(a, b);
    return *(uint32_t*)&h;
}
// MUFU 2^x — 1 issue slot; |rel err| ~2^-22; returns 0 for very negative x.
__device__ __forceinline__ float ex2f(float x) {
    float y;
    asm("ex2.approx.f32 %0, %1;" : "=f"(y) : "f"(x));
    return y;
}

// ---------------------------------------------------------------------------
// Fused prep kernel (unchanged from R16).
// ---------------------------------------------------------------------------
#define PREP_CONVX_BLOCKS 8192
#define PREP_WT_BLOCKS    4096
#define PREP_CS_BLOCKS    256
#define PREP_BLOCKS (PREP_CONVX_BLOCKS + PREP_WT_BLOCKS + PREP_CS_BLOCKS)

__global__ __launch_bounds__(256)
void prep_kernel(const float* __restrict__ x,
                 const float* __restrict__ Wq, const float* __restrict__ Wk,
                 const float* __restrict__ Wv, const float* __restrict__ Wo)
{
    __shared__ float ts[32][33];
    const int bid = blockIdx.x;
    const int tid = threadIdx.x;

    if (bid < PREP_CONVX_BLOCKS) {
        int i = bid * 256 + tid;                 // float4 index
        float4 v = ((const float4*)x)[i];
        __half2* h2 = (__half2*)g_Xhi;
        h2[2 * i]     = __floats2half2_rn(v.x, v.y);
        h2[2 * i + 1] = __floats2half2_rn(v.z, v.w);
    } else if (bid < PREP_CONVX_BLOCKS + PREP_WT_BLOCKS) {
        int wb = bid - PREP_CONVX_BLOCKS;
        int z  = wb >> 10;                       // 0..3
        int t2 = wb & 1023;
        int by = t2 >> 5, bx = t2 & 31;
        const float* W = (z == 0) ? Wq : (z == 1) ? Wk : (z == 2) ? Wv : Wo;
        int k0 = by * 32, n0 = bx * 32;
        int tx = tid & 31, ty = tid >> 5;
#pragma unroll
        for (int r = 0; r < 32; r += 8)
            ts[ty + r][tx] = W[(size_t)(k0 + ty + r) * Dm + n0 + tx];
        __syncthreads();
#pragma unroll
        for (int r = 0; r < 32; r += 8) {
            float v = ts[tx][ty + r];
            size_t o = (size_t)z * Dm * Dm + (size_t)(n0 + ty + r) * Dm + k0 + tx;
            g_Wth[o] = __float2half_rn(v);
        }
    } else {
        int i  = (bid - PREP_CONVX_BLOCKS - PREP_WT_BLOCKS) * 256 + tid;
        int ip = i >> 11, pos = i & (Sq - 1);
        float invf = (float)exp(-(double)(2 * ip) * (log(10000.0) / 64.0));
        float sn, cn;
        sincosf((float)pos * invf, &sn, &cn);
        g_cs[i] = make_float2(cn, sn);
    }
}

// ---------------------------------------------------------------------------
// mma.sync fp16 GEMM (R13/R16 frozen mainloop).
// MODE: 0 = f32 out (oproj); 1 = RoPE+scale fp16 out (Q);
//       2 = RoPE fp16 out (K); 3 = fp16 out (V)
// ---------------------------------------------------------------------------
#define KC 32
#define NCHUNK (Dm / KC)        // 32
#define ROWB 80
#define STG_MAT (128 * ROWB)    // 10240
#define STG_SIZE (2 * STG_MAT)  // 20480 : A, B
#define GEMM_SMEM (2 * STG_SIZE)  // 40960

__device__ __forceinline__ void load_chunk(uint32_t sb,
    const __half* __restrict__ A, const __half* __restrict__ B,
    int m0, int n0, int kc, int tid)
{
    const __half* srcs[2] = { A + (size_t)m0 * Dm + kc, B + (size_t)n0 * Dm + kc };
    const int row = (tid >> 2);
    const int s   = tid & 3;
#pragma unroll
    for (int j = 0; j < 4; ++j) {
        const int mat = j >> 1;
        const int r   = (j & 1) * 64 + row;
        cp16(sb + mat * STG_MAT + r * ROWB + s * 16,
             (const char*)(srcs[mat] + (size_t)r * Dm) + s * 16);
    }
}

__device__ __forceinline__ void gemm_frags(uint32_t aBase, uint32_t bBase, int s,
                                           uint32_t (*ah)[4], uint32_t (*bh)[2])
{
#pragma unroll
    for (int mt = 0; mt < 4; ++mt)
        ldmx4(ah[mt], aBase + mt * (16 * ROWB) + s * 32);
#pragma unroll
    for (int p = 0; p < 2; ++p) {
        uint32_t t[4];
        ldmx4(t, bBase + p * (16 * ROWB) + s * 32);
        bh[2 * p][0] = t[0]; bh[2 * p][1] = t[1];
        bh[2 * p + 1][0] = t[2]; bh[2 * p + 1][1] = t[3];
    }
}

__device__ __forceinline__ void gemm_mmas(float (*acc)[4][4],
                                          uint32_t (*ah)[4], uint32_t (*bh)[2])
{
#pragma unroll
    for (int mt = 0; mt < 4; ++mt)
#pragma unroll
        for (int nt = 0; nt < 4; ++nt)
            mma16816(acc[mt][nt], ah[mt], bh[nt]);
}

template <int MODE>
__device__ __forceinline__ void gemm_mma(const __half* __restrict__ A,
                                         const __half* __restrict__ B,
                                         float* __restrict__ Cf,
                                         __half* __restrict__ Ch)
{
    extern __shared__ char smraw[];
    const uint32_t sbase = smem_u32(smraw);

    const int tid  = threadIdx.x;
    const int wid  = tid >> 5, lane = tid & 31;
    const int wm   = wid & 1, wn = wid >> 1;
    const int m0   = blockIdx.y * 128, n0 = blockIdx.x * 128;

    const uint32_t aLaneOff = (lane & 15) * ROWB + (lane >> 4) * 16;
    const uint32_t bLaneOff = ((lane >> 4) * 8 + (lane & 7)) * ROWB + ((lane >> 3) & 1) * 16;

    float acc[4][4][4];
#pragma unroll
    for (int mt = 0; mt < 4; ++mt)
#pragma unroll
        for (int nt = 0; nt < 4; ++nt)
#pragma unroll
            for (int q = 0; q < 4; ++q) acc[mt][nt][q] = 0.0f;

#pragma unroll
    for (int c = 0; c < 2; ++c) {
        load_chunk(sbase + c * STG_SIZE, A, B, m0, n0, c * KC, tid);
        asm volatile("cp.async.commit_group;" ::: "memory");
    }

    for (int i = 0; i < NCHUNK; ++i) {
        asm volatile("cp.async.wait_group 1;" ::: "memory");
        __syncthreads();

        const uint32_t sb = sbase + (i & 1) * STG_SIZE;
        const uint32_t aBase = sb + (wm * 64) * ROWB + aLaneOff;
        const uint32_t bBase = sb + STG_MAT + (wn * 32) * ROWB + bLaneOff;

        // ---- k16 step 0: frags -> MMAs
        {
            uint32_t ah[4][4], bh[4][2];
            gemm_frags(aBase, bBase, 0, ah, bh);
            gemm_mmas(acc, ah, bh);
        }
        // ---- k16 step 1: frags -> barrier -> refill (overlaps MMAs) -> MMAs
        {
            uint32_t ah[4][4], bh[4][2];
            gemm_frags(aBase, bBase, 1, ah, bh);
            __syncthreads();   // all smem reads of this chunk complete
            if (i + 2 < NCHUNK)
                load_chunk(sbase + (i & 1) * STG_SIZE, A, B, m0, n0, (i + 2) * KC, tid);
            asm volatile("cp.async.commit_group;" ::: "memory");
            gemm_mmas(acc, ah, bh);
        }
    }

#pragma unroll
    for (int mt = 0; mt < 4; ++mt) {
        const int r = m0 + wm * 64 + mt * 16 + (lane >> 2);
#pragma unroll
        for (int nt = 0; nt < 4; ++nt) {
            const int c = n0 + wn * 32 + nt * 8 + (lane & 3) * 2;
            float v0 = acc[mt][nt][0], v1 = acc[mt][nt][1];
            float v2 = acc[mt][nt][2], v3 = acc[mt][nt][3];
            if (MODE == 1 || MODE == 2) {
                const int ip = (c & (HD - 1)) >> 1;
                float2 cs0 = g_cs[ip * Sq + (r & (Sq - 1))];
                float2 cs8 = g_cs[ip * Sq + ((r + 8) & (Sq - 1))];
                float t0 = v0 * cs0.x - v1 * cs0.y;
                float t1 = v0 * cs0.y + v1 * cs0.x;
                float t2 = v2 * cs8.x - v3 * cs8.y;
                float t3 = v2 * cs8.y + v3 * cs8.x;
                v0 = t0; v1 = t1; v2 = t2; v3 = t3;
            }
            if (MODE == 1) { v0 *= QSCALE; v1 *= QSCALE; v2 *= QSCALE; v3 *= QSCALE; }
            if (MODE == 0) {
                *(float2*)(Cf + (size_t)r * Dm + c)       = make_float2(v0, v1);
                *(float2*)(Cf + (size_t)(r + 8) * Dm + c) = make_float2(v2, v3);
            } else {
                *(__half2*)(Ch + (size_t)r * Dm + c)       = __floats2half2_rn(v0, v1);
                *(__half2*)(Ch + (size_t)(r + 8) * Dm + c) = __floats2half2_rn(v2, v3);
            }
        }
    }
}

__global__ __launch_bounds__(256, 2)
void qkv_mma_kernel() {
    const int z = blockIdx.z;
    const __half* Bh = g_Wth + (size_t)z * Dm * Dm;
    if (z == 0)      gemm_mma<1>(g_Xhi, Bh, nullptr, g_Qh);
    else if (z == 1) gemm_mma<2>(g_Xhi, Bh, nullptr, g_Kh);
    else             gemm_mma<3>(g_Xhi, Bh, nullptr, g_Vh);
}

__global__ __launch_bounds__(256, 2)
void oproj_mma_kernel(float* __restrict__ out) {
    gemm_mma<0>(g_Oh, g_Wth + (size_t)3 * Dm * Dm, out, nullptr);
}

// ---------------------------------------------------------------------------
// mma.sync flash attention. Br=128, Bk=64, hd=64. Single-pass QK and PV,
// log2-domain softmax (MUFU ex2). Row-sum l computed BY THE TENSOR CORE:
// a constant ones-column B-fragment turns 4 extra MMAs/tile into the exact
// online-softmax l update (lacc shares the oacc rescale). 3-stage KV ring:
// one barrier per tile.
// ---------------------------------------------------------------------------
#define FROWB 144                       // 64 halfs = 128B data + 16B pad
#define FQH_OFF 0
#define FST_OFF (128 * FROWB)           // 18432
#define FMAT (64 * FROWB)               // 9216
#define FST_SIZE (2 * FMAT)             // 18432 : Kh, Vh
#define FLASH_SMEM (FST_OFF + 3 * FST_SIZE)   // 73728

__device__ __forceinline__ void flash_load_kv(uint32_t sb, int kRow0, int h, int tid) {
    const __half* srcs[2] = { g_Kh, g_Vh };
#pragma unroll
    for (int j = 0; j < 4; ++j) {
        int it  = j * 256 + tid;          // 0..1023
        int mat = it >> 9;
        int row = (it >> 3) & 63;
        int seg = it & 7;
        cp16(sb + mat * FMAT + row * FROWB + seg * 16,
             srcs[mat] + (size_t)(kRow0 + row) * Dm + h * HD + seg * 8);
    }
}

__global__ __launch_bounds__(256, 2)
void flash_mma_kernel()
{
    extern __shared__ char smraw[];
    const uint32_t sbase = smem_u32(smraw);

    const int tid  = threadIdx.x;
    const int w    = tid >> 5, lane = tid & 31;
    const int bh   = blockIdx.y;
    const int b    = bh >> 4, h = bh & 15;
    const int qb   = gridDim.x - 1 - blockIdx.x;    // heavy blocks first
    const int q0   = qb * 128;
    const int qRow0 = b * Sq + q0;
    const int nkt  = 2 * qb + 2;

    const uint32_t aLaneOff = (lane & 15) * FROWB + (lane >> 4) * 16;
    const uint32_t bLaneOff = ((lane >> 4) * 8 + (lane & 7)) * FROWB + ((lane >> 3) & 1) * 16;

    // Ones-column B fragment (n8k16, col 0 = 1.0, cols 1..7 = 0):
    // lanes 0..3 hold col 0 -> packed {1.0h,1.0h}; all other lanes 0.
    uint32_t onesb[2];
    onesb[0] = (lane < 4) ? 0x3C003C00u : 0u;
    onesb[1] = onesb[0];

    // Group 0: Q + KV tile 0. Group 1: KV tile 1 (always exists; nkt >= 2).
#pragma unroll
    for (int j = 0; j < 4; ++j) {
        int it = j * 256 + tid;            // 0..1023
        int row = it >> 3, seg = it & 7;
        cp16(sbase + FQH_OFF + row * FROWB + seg * 16,
             g_Qh + (size_t)(qRow0 + row) * Dm + h * HD + seg * 8);
    }
    flash_load_kv(sbase + FST_OFF, b * Sq, h, tid);
    asm volatile("cp.async.commit_group;" ::: "memory");
    flash_load_kv(sbase + FST_OFF + FST_SIZE, b * Sq + 64, h, tid);
    asm volatile("cp.async.commit_group;" ::: "memory");

    uint32_t qh[4][4];
    float oacc[8][4];
#pragma unroll
    for (int nt = 0; nt < 8; ++nt)
#pragma unroll
        for (int q = 0; q < 4; ++q) oacc[nt][q] = 0.0f;
    float lacc[4] = {0.f, 0.f, 0.f, 0.f};   // tensor-core row sums (col 0 lanes)
    float m0 = -1e30f, m1 = -1e30f;
    const int qrow = q0 + w * 16 + (lane >> 2);   // seq pos of row r (r+8 = +8)

    int buf = 0;
    for (int kt = 0; kt < nkt; ++kt) {
        asm volatile("cp.async.wait_group 1;" ::: "memory");
        __syncthreads();   // tile kt ready; buffer (kt+2)%3 fully consumed

        if (kt == 0) {   // Q fragments (arrived with group 0)
            const uint32_t qBaseH = sbase + FQH_OFF + (w * 16) * FROWB + aLaneOff;
#pragma unroll
            for (int j = 0; j < 4; ++j)
                ldmx4(qh[j], qBaseH + j * 32);
        }

        const int nbuf = (buf + 2 >= 3) ? buf - 1 : buf + 2;
        if (kt + 2 < nkt)
            flash_load_kv(sbase + FST_OFF + nbuf * FST_SIZE,
                          b * Sq + (kt + 2) * 64, h, tid);
        asm volatile("cp.async.commit_group;" ::: "memory");

        const uint32_t sb = sbase + FST_OFF + buf * FST_SIZE;

        // ---- S = Q K^T (log2 units) ----
        float sacc[8][4];
#pragma unroll
        for (int nt = 0; nt < 8; ++nt)
#pragma unroll
            for (int q = 0; q < 4; ++q) sacc[nt][q] = 0.0f;

#pragma unroll
        for (int p = 0; p < 4; ++p) {
            const uint32_t kBase = sb + p * (16 * FROWB) + bLaneOff;
#pragma unroll
            for (int j = 0; j < 4; ++j) {
                uint32_t kh[4];
                ldmx4(kh, kBase + j * 32);
                mma16816(sacc[2 * p],     qh[j], kh);
                mma16816(sacc[2 * p + 1], qh[j], kh + 2);
            }
        }

        // ---- causal mask (diagonal-overlap tiles only) ----
        if (kt >= 2 * qb) {
#pragma unroll
            for (int nt = 0; nt < 8; ++nt) {
                const int col = kt * 64 + nt * 8 + (lane & 3) * 2;
                if (col     > qrow)     sacc[nt][0] = -1e30f;
                if (col + 1 > qrow)     sacc[nt][1] = -1e30f;
                if (col     > qrow + 8) sacc[nt][2] = -1e30f;
                if (col + 1 > qrow + 8) sacc[nt][3] = -1e30f;
            }
        }

        // ---- online softmax: quad-global max; exp; rescale (incl. lacc) ----
        float mx0 = -1e30f, mx1 = -1e30f;
#pragma unroll
        for (int nt = 0; nt < 8; ++nt) {
            mx0 = fmaxf(mx0, fmaxf(sacc[nt][0], sacc[nt][1]));
            mx1 = fmaxf(mx1, fmaxf(sacc[nt][2], sacc[nt][3]));
        }
        mx0 = fmaxf(mx0, __shfl_xor_sync(0xffffffffu, mx0, 1, 4));
        mx0 = fmaxf(mx0, __shfl_xor_sync(0xffffffffu, mx0, 2, 4));
        mx1 = fmaxf(mx1, __shfl_xor_sync(0xffffffffu, mx1, 1, 4));
        mx1 = fmaxf(mx1, __shfl_xor_sync(0xffffffffu, mx1, 2, 4));
        const float mn0 = fmaxf(m0, mx0), mn1 = fmaxf(m1, mx1);
        const float al0 = ex2f(m0 - mn0), al1 = ex2f(m1 - mn1);
        m0 = mn0;  m1 = mn1;
#pragma unroll
        for (int nt = 0; nt < 8; ++nt) {
            sacc[nt][0] = ex2f(sacc[nt][0] - mn0);
            sacc[nt][1] = ex2f(sacc[nt][1] - mn0);
            sacc[nt][2] = ex2f(sacc[nt][2] - mn1);
            sacc[nt][3] = ex2f(sacc[nt][3] - mn1);
        }
#pragma unroll
        for (int nt = 0; nt < 8; ++nt) {
            oacc[nt][0] *= al0; oacc[nt][1] *= al0;
            oacc[nt][2] *= al1; oacc[nt][3] *= al1;
        }
        lacc[0] *= al0; lacc[1] *= al0;
        lacc[2] *= al1; lacc[3] *= al1;

        // ---- P fragments ----
        uint32_t aP[4][4];
#pragma unroll
        for (int j = 0; j < 4; ++j) {
            aP[j][0] = packh2(sacc[2 * j][0],     sacc[2 * j][1]);
            aP[j][1] = packh2(sacc[2 * j][2],     sacc[2 * j][3]);
            aP[j][2] = packh2(sacc[2 * j + 1][0], sacc[2 * j + 1][1]);
            aP[j][3] = packh2(sacc[2 * j + 1][2], sacc[2 * j + 1][3]);
        }

        // ---- O += P V ; l += P * ones (tensor-core row sum) ----
#pragma unroll
        for (int p = 0; p < 4; ++p) {
#pragma unroll
            for (int j = 0; j < 4; ++j) {
                uint32_t vh[4];
                ldmx4t(vh, sb + FMAT + j * (16 * FROWB) + p * 32 + aLaneOff);
                mma16816(oacc[2 * p],     aP[j], vh);
                mma16816(oacc[2 * p + 1], aP[j], vh + 2);
            }
        }
#pragma unroll
        for (int j = 0; j < 4; ++j)
            mma16816(lacc, aP[j], onesb);

        buf = (buf + 1 >= 3) ? 0 : buf + 1;
    }

    // ---- epilogue: broadcast l from quad lane 0, normalize, fp16 store ----
    const float ls0 = __shfl_sync(0xffffffffu, lacc[0], 0, 4);  // row r sum
    const float ls1 = __shfl_sync(0xffffffffu, lacc[2], 0, 4);  // row r+8 sum
    const float inv0 = 1.0f / ls0, inv1 = 1.0f / ls1;
    const size_t grow0 = (size_t)(b * Sq + qrow);
    const size_t grow1 = grow0 + 8;
#pragma unroll
    for (int nt = 0; nt < 8; ++nt) {
        const int col = h * HD + nt * 8 + (lane & 3) * 2;
        *(__half2*)(g_Oh + grow0 * Dm + col) =
            __floats2half2_rn(oacc[nt][0] * inv0, oacc[nt][1] * inv0);
        *(__half2*)(g_Oh + grow1 * Dm + col) =
            __floats2half2_rn(oacc[nt][2] * inv1, oacc[nt][3] * inv1);
    }
}

// ---------------------------------------------------------------------------
extern "C" void kernel_launch(void* const* d_in, const int* in_sizes, int n_in,
                              void* d_out, int out_size)
{
    const float* x   = (const float*)d_in[0];
    const float* Wq  = (const float*)d_in[1];
    const float* Wk  = (const float*)d_in[2];
    const float* Wv  = (const float*)d_in[3];
    const float* Wo  = (const float*)d_in[4];
    float*       out = (float*)d_out;

    cudaFuncSetAttribute(qkv_mma_kernel, cudaFuncAttributeMaxDynamicSharedMemorySize,
                         GEMM_SMEM);
    cudaFuncSetAttribute(oproj_mma_kernel, cudaFuncAttributeMaxDynamicSharedMemorySize,
                         GEMM_SMEM);
    cudaFuncSetAttribute(flash_mma_kernel, cudaFuncAttributeMaxDynamicSharedMemorySize,
                         FLASH_SMEM);

    // 1) Fused prep: X->fp16, W^T->fp16, RoPE table — one launch
    prep_kernel<<<PREP_BLOCKS, 256>>>(x, Wq, Wk, Wv, Wo);

    // 2) Q/K/V projections (HMMA fp16; Q rope+scale, K rope)
    qkv_mma_kernel<<<dim3(Dm / 128, MT / 128, 3), 256, GEMM_SMEM>>>();

    // 3) Causal flash attention on HMMA
    flash_mma_kernel<<<dim3(Sq / 128, Bc * Hh), 256, FLASH_SMEM>>>();

    // 4) Output projection (fp16 single pass, f32 out)
    oproj_mma_kernel<<<dim3(Dm / 128, MT / 128), 256, GEMM_SMEM>>>(out);
}